// round 2
// baseline (speedup 1.0000x reference)
#include <cuda_runtime.h>
#include <math.h>

#define LVL 4
#define BAT 128
#define INW 512
#define CTXW 512
#define STW 512
#define RW 256
#define CW 256
#define DW 1536
#define H_SIZE (LVL*BAT*STW)          /* 262144 */
#define M_LVL_STRIDE (BAT*RW*CW)      /* 8388608 */

// scratch (allocation-free rule: __device__ globals)
__device__ __align__(16) float g_gate[3][LVL][BAT][STW];  // phi/alpha/beta raw (3 MB)
__device__ __align__(16) float g_uv[2][LVL][BAT][RW];     // u,v raw (1 MB)

__device__ __forceinline__ float sigmoidf_(float x) { return 1.0f / (1.0f + __expf(-x)); }

// ---------------------------------------------------------------------------
// Tiled fp32 GEMM for the 3 gates. O[l,b,o] = sum_d gi[l,b,d] * W[l,o,d] + bias
// gi[b,d] = x|c|h[l] piecewise along d (segments are 512-aligned, BK=16 never
// straddles a boundary).
// Block tile 64x64, BK=16, 256 threads, 4x4 per thread.
// grid: (ntile=8, mtile=2, z = l*3+gate)
// ---------------------------------------------------------------------------
__global__ __launch_bounds__(256)
void gate_gemm(const float* __restrict__ x, const float* __restrict__ c,
               const float* __restrict__ h,
               const float* __restrict__ phi_w, const float* __restrict__ alpha_w,
               const float* __restrict__ beta_w,
               const float* __restrict__ phi_b, const float* __restrict__ alpha_b,
               const float* __restrict__ beta_b)
{
    const int zz = blockIdx.z;
    const int l = zz / 3, gate = zz % 3;
    const int mtile = blockIdx.y;   // 0..1 (b)
    const int ntile = blockIdx.x;   // 0..7 (o)

    const float* W    = (gate == 0 ? phi_w : gate == 1 ? alpha_w : beta_w) + (size_t)l * STW * DW;
    const float* bias = (gate == 0 ? phi_b : gate == 1 ? alpha_b : beta_b) + l * STW;

    __shared__ float As[16][64];
    __shared__ float Bs[16][64];

    const int t   = threadIdx.x;
    const int row = t >> 2;          // 0..63 (load row)
    const int k4  = (t & 3) << 2;    // 0,4,8,12 (load k offset)
    const int tx  = t & 15;          // n-thread
    const int ty  = t >> 4;          // m-thread

    float acc[4][4] = {};

    const int b_g = mtile * 64 + row;   // global batch row for A load
    const int o_g = ntile * 64 + row;   // global out row for B load

    for (int kt = 0; kt < DW; kt += 16) {
        const int kg = kt + k4;
        const float* aptr;
        if (kg < INW)            aptr = x + (size_t)b_g * INW + kg;
        else if (kg < INW + CTXW) aptr = c + (size_t)b_g * CTXW + (kg - INW);
        else                      aptr = h + ((size_t)l * BAT + b_g) * STW + (kg - INW - CTXW);
        float4 av = *(const float4*)aptr;
        As[k4 + 0][row] = av.x; As[k4 + 1][row] = av.y;
        As[k4 + 2][row] = av.z; As[k4 + 3][row] = av.w;

        float4 bv = *(const float4*)(W + (size_t)o_g * DW + kt + k4);
        Bs[k4 + 0][row] = bv.x; Bs[k4 + 1][row] = bv.y;
        Bs[k4 + 2][row] = bv.z; Bs[k4 + 3][row] = bv.w;
        __syncthreads();

        #pragma unroll
        for (int kk = 0; kk < 16; kk++) {
            float4 a = *(const float4*)&As[kk][ty * 4];
            float4 w = *(const float4*)&Bs[kk][tx * 4];
            float am[4] = {a.x, a.y, a.z, a.w};
            float wn[4] = {w.x, w.y, w.z, w.w};
            #pragma unroll
            for (int i = 0; i < 4; i++)
                #pragma unroll
                for (int j = 0; j < 4; j++)
                    acc[i][j] = fmaf(am[i], wn[j], acc[i][j]);
        }
        __syncthreads();
    }

    const int b0 = mtile * 64 + ty * 4;
    const int o0 = ntile * 64 + tx * 4;
    #pragma unroll
    for (int i = 0; i < 4; i++)
        #pragma unroll
        for (int j = 0; j < 4; j++)
            g_gate[gate][l][b0 + i][o0 + j] = acc[i][j] + bias[o0 + j];
}

// ---------------------------------------------------------------------------
// h_new = sigmoid(alpha) * tanh(phi) + sigmoid(beta) * h    -> d_out[0:H_SIZE]
// ---------------------------------------------------------------------------
__global__ __launch_bounds__(256)
void hnew_kernel(const float* __restrict__ h, float* __restrict__ out)
{
    const int idx = blockIdx.x * blockDim.x + threadIdx.x;
    if (idx >= H_SIZE) return;
    const float* g = &g_gate[0][0][0][0];
    float phi   = g[idx];
    float alpha = g[H_SIZE + idx];
    float beta  = g[2 * H_SIZE + idx];
    out[idx] = sigmoidf_(alpha) * tanhf(phi) + sigmoidf_(beta) * h[idx];
}

// ---------------------------------------------------------------------------
// u/v GEMM. wv[b,d] = h_new|x|c piecewise. N=256.
// grid: (ntile=4, mtile=2, z = l*2+which)  which: 0=u, 1=v
// ---------------------------------------------------------------------------
__global__ __launch_bounds__(256)
void uv_gemm(const float* __restrict__ hn, const float* __restrict__ x,
             const float* __restrict__ c,
             const float* __restrict__ u_w, const float* __restrict__ v_w,
             const float* __restrict__ u_b, const float* __restrict__ v_b)
{
    const int zz = blockIdx.z;
    const int l = zz >> 1, which = zz & 1;
    const int mtile = blockIdx.y;
    const int ntile = blockIdx.x;

    const float* W    = (which ? v_w : u_w) + (size_t)l * RW * DW;
    const float* bias = (which ? v_b : u_b) + l * RW;

    __shared__ float As[16][64];
    __shared__ float Bs[16][64];

    const int t   = threadIdx.x;
    const int row = t >> 2;
    const int k4  = (t & 3) << 2;
    const int tx  = t & 15;
    const int ty  = t >> 4;

    float acc[4][4] = {};

    const int b_g = mtile * 64 + row;
    const int o_g = ntile * 64 + row;

    for (int kt = 0; kt < DW; kt += 16) {
        const int kg = kt + k4;
        const float* aptr;
        if (kg < STW)             aptr = hn + ((size_t)l * BAT + b_g) * STW + kg;
        else if (kg < STW + INW)  aptr = x + (size_t)b_g * INW + (kg - STW);
        else                      aptr = c + (size_t)b_g * CTXW + (kg - STW - INW);
        float4 av = *(const float4*)aptr;
        As[k4 + 0][row] = av.x; As[k4 + 1][row] = av.y;
        As[k4 + 2][row] = av.z; As[k4 + 3][row] = av.w;

        float4 bv = *(const float4*)(W + (size_t)o_g * DW + kt + k4);
        Bs[k4 + 0][row] = bv.x; Bs[k4 + 1][row] = bv.y;
        Bs[k4 + 2][row] = bv.z; Bs[k4 + 3][row] = bv.w;
        __syncthreads();

        #pragma unroll
        for (int kk = 0; kk < 16; kk++) {
            float4 a = *(const float4*)&As[kk][ty * 4];
            float4 w = *(const float4*)&Bs[kk][tx * 4];
            float am[4] = {a.x, a.y, a.z, a.w};
            float wn[4] = {w.x, w.y, w.z, w.w};
            #pragma unroll
            for (int i = 0; i < 4; i++)
                #pragma unroll
                for (int j = 0; j < 4; j++)
                    acc[i][j] = fmaf(am[i], wn[j], acc[i][j]);
        }
        __syncthreads();
    }

    const int b0 = mtile * 64 + ty * 4;
    const int o0 = ntile * 64 + tx * 4;
    #pragma unroll
    for (int i = 0; i < 4; i++)
        #pragma unroll
        for (int j = 0; j < 4; j++)
            g_uv[which][l][b0 + i][o0 + j] = acc[i][j] + bias[o0 + j];
}

// ---------------------------------------------------------------------------
// M update, fused across all 4 levels so each M element is read exactly once:
// M_new[l] = (1-g)*M[l] + 0.5*g*(M[lu]+M[ld]) + e * u[l][i] * v[l][j]
// grid: (ichunk=8, b=128), 256 threads, float4 per thread.
// ---------------------------------------------------------------------------
__global__ __launch_bounds__(256)
void m_update(const float* __restrict__ M,
              const float* __restrict__ gamma_logits,
              const float* __restrict__ eta_logits,
              float* __restrict__ out)
{
    __shared__ float sv[4][256];
    __shared__ float su[4][32];
    __shared__ float sg[4], se[4];

    const int b  = blockIdx.y;
    const int ic = blockIdx.x;     // 0..7: 32-row chunk of i
    const int t  = threadIdx.x;

    for (int e = t; e < 1024; e += 256) {
        int l = e >> 8, j = e & 255;
        sv[l][j] = g_uv[1][l][b][j];
    }
    if (t < 128) {
        int l = t >> 5, i = t & 31;
        su[l][i] = g_uv[0][l][b][ic * 32 + i];
    }
    if (t < 4) { sg[t] = sigmoidf_(gamma_logits[t]); se[t] = sigmoidf_(eta_logits[t]); }
    __syncthreads();

    float* mout = out + H_SIZE;

    #pragma unroll 1
    for (int it = 0; it < 8; it++) {
        const int p  = it * 256 + t;
        const int i  = p >> 6;              // 0..31
        const int j4 = (p & 63) << 2;       // 0..252
        const int ig = ic * 32 + i;
        const size_t base = ((size_t)b * RW + ig) * CW + j4;   // within-level offset

        float4 m[4];
        #pragma unroll
        for (int l = 0; l < 4; l++)
            m[l] = *(const float4*)(M + (size_t)l * M_LVL_STRIDE + base);

        #pragma unroll
        for (int l = 0; l < 4; l++) {
            const int lu = (l == 0) ? 0 : l - 1;
            const int ld = (l == 3) ? 3 : l + 1;
            const float g = sg[l], e = se[l];
            const float uval = su[l][i];
            const float4 v = *(const float4*)&sv[l][j4];
            float4 o;
            o.x = (1.0f - g) * m[l].x + 0.5f * g * (m[lu].x + m[ld].x) + e * uval * v.x;
            o.y = (1.0f - g) * m[l].y + 0.5f * g * (m[lu].y + m[ld].y) + e * uval * v.y;
            o.z = (1.0f - g) * m[l].z + 0.5f * g * (m[lu].z + m[ld].z) + e * uval * v.z;
            o.w = (1.0f - g) * m[l].w + 0.5f * g * (m[lu].w + m[ld].w) + e * uval * v.w;
            *(float4*)(mout + (size_t)l * M_LVL_STRIDE + base) = o;
        }
    }
}

// ---------------------------------------------------------------------------
extern "C" void kernel_launch(void* const* d_in, const int* in_sizes, int n_in,
                              void* d_out, int out_size)
{
    const float* x       = (const float*)d_in[0];
    const float* c       = (const float*)d_in[1];
    const float* h       = (const float*)d_in[2];
    const float* M       = (const float*)d_in[3];
    const float* phi_w   = (const float*)d_in[4];
    const float* phi_b   = (const float*)d_in[5];
    const float* alpha_w = (const float*)d_in[6];
    const float* alpha_b = (const float*)d_in[7];
    const float* beta_w  = (const float*)d_in[8];
    const float* beta_b  = (const float*)d_in[9];
    const float* u_w     = (const float*)d_in[10];
    const float* u_b     = (const float*)d_in[11];
    const float* v_w     = (const float*)d_in[12];
    const float* v_b     = (const float*)d_in[13];
    const float* gamma_l = (const float*)d_in[14];
    const float* eta_l   = (const float*)d_in[15];

    float* out = (float*)d_out;

    // 1. gate GEMMs -> g_gate
    gate_gemm<<<dim3(8, 2, 12), 256>>>(x, c, h, phi_w, alpha_w, beta_w,
                                       phi_b, alpha_b, beta_b);
    // 2. h_new -> d_out[0:H_SIZE]
    hnew_kernel<<<H_SIZE / 256, 256>>>(h, out);
    // 3. u/v GEMMs (read h_new from d_out) -> g_uv
    uv_gemm<<<dim3(4, 2, 8), 256>>>(out, x, c, u_w, v_w, u_b, v_b);
    // 4. fused 4-level M update -> d_out[H_SIZE:]
    m_update<<<dim3(8, 128), 256>>>(M, gamma_l, eta_l, out);
}

// round 4
// speedup vs baseline: 1.9022x; 1.9022x over previous
#include <cuda_runtime.h>
#include <math.h>

#define LVL 4
#define BAT 128
#define INW 512
#define CTXW 512
#define STW 512
#define RW 256
#define CW 256
#define DW 1536
#define KC 32
#define H_SIZE (LVL*BAT*STW)          /* 262144 */
#define M_LVL_STRIDE (BAT*RW*CW)      /* 8388608 */

// scratch (allocation-free rule: __device__ globals)
__device__ __align__(16) float g_uv[2][LVL][BAT][RW];     // u,v raw (1 MB)

__device__ __forceinline__ float sigmoidf_(float x) { return 1.0f / (1.0f + __expf(-x)); }

__device__ __forceinline__ unsigned f2tf(float x) {
    unsigned r;
    asm("cvt.rna.tf32.f32 %0, %1;" : "=r"(r) : "f"(x));
    return r;
}

__device__ __forceinline__ void mma_tf32(float* d, unsigned a0, unsigned a1,
                                         unsigned a2, unsigned a3,
                                         unsigned b0, unsigned b1)
{
    asm volatile(
        "mma.sync.aligned.m16n8k8.row.col.f32.tf32.tf32.f32 "
        "{%0,%1,%2,%3}, {%4,%5,%6,%7}, {%8,%9}, {%0,%1,%2,%3};\n"
        : "+f"(d[0]), "+f"(d[1]), "+f"(d[2]), "+f"(d[3])
        : "r"(a0), "r"(a1), "r"(a2), "r"(a3), "r"(b0), "r"(b1));
}

// ---------------------------------------------------------------------------
// Fused gate GEMM (phi/alpha/beta share A tile) + h_new epilogue.
// O[l,b,o] = act( sum_d gi[l,b,d] * W_gate[l,o,d] + bias );  gi = x|c|h[l]
// h_new = sigmoid(alpha)*tanh(phi) + sigmoid(beta)*h -> out[0:H_SIZE]
// Block: M=32 (batch), O=64 per gate x 3 gates. 256 threads (8 warps).
// Warp tile: 16(M) x 16(O) per gate -> mma m16n8k8: 1x2 tiles x 3 gates.
// grid: (otile=8, mtile=4, l=4) = 128 blocks.
// ---------------------------------------------------------------------------
__global__ __launch_bounds__(256)
void gate_hnew(const float* __restrict__ x, const float* __restrict__ c,
               const float* __restrict__ h,
               const float* __restrict__ phi_w, const float* __restrict__ alpha_w,
               const float* __restrict__ beta_w,
               const float* __restrict__ phi_b, const float* __restrict__ alpha_b,
               const float* __restrict__ beta_b,
               float* __restrict__ out)
{
    __shared__ unsigned As[32][KC + 1];
    __shared__ unsigned Bs[3][64][KC + 1];

    const int l = blockIdx.z;
    const int mtile = blockIdx.y;
    const int otile = blockIdx.x;
    const int t = threadIdx.x;
    const int lane = t & 31, w = t >> 5;
    const int wm = w >> 2, wn = w & 3;     // wm: 0..1 (x16 rows), wn: 0..3 (x16 cols)
    const int g = lane >> 2, tg = lane & 3;

    const float* Wg[3] = { phi_w   + (size_t)l * STW * DW,
                           alpha_w + (size_t)l * STW * DW,
                           beta_w  + (size_t)l * STW * DW };

    // loader indices
    const int ar  = t >> 3;             // 0..31
    const int ac4 = (t & 7) << 2;       // 0..28
    const int b_g = mtile * 32 + ar;

    float4 aReg;
    float4 bReg[3][2];

    float acc[3][2][4];
    #pragma unroll
    for (int ga = 0; ga < 3; ga++)
        #pragma unroll
        for (int ni = 0; ni < 2; ni++)
            #pragma unroll
            for (int r = 0; r < 4; r++) acc[ga][ni][r] = 0.0f;

    // prefetch chunk 0
    {
        const int kg = ac4;  // kt = 0, always in x segment
        aReg = *(const float4*)(x + (size_t)b_g * INW + kg);
        #pragma unroll
        for (int ga = 0; ga < 3; ga++)
            #pragma unroll
            for (int i = 0; i < 2; i++) {
                const int idx = i * 256 + t;
                const int r = idx >> 3, c4 = (idx & 7) << 2;
                bReg[ga][i] = *(const float4*)(Wg[ga] + (size_t)(otile * 64 + r) * DW + c4);
            }
    }

    for (int kt = 0; kt < DW; kt += KC) {
        // stage regs -> smem (tf32 rounded)
        As[ar][ac4 + 0] = f2tf(aReg.x); As[ar][ac4 + 1] = f2tf(aReg.y);
        As[ar][ac4 + 2] = f2tf(aReg.z); As[ar][ac4 + 3] = f2tf(aReg.w);
        #pragma unroll
        for (int ga = 0; ga < 3; ga++)
            #pragma unroll
            for (int i = 0; i < 2; i++) {
                const int idx = i * 256 + t;
                const int r = idx >> 3, c4 = (idx & 7) << 2;
                Bs[ga][r][c4 + 0] = f2tf(bReg[ga][i].x);
                Bs[ga][r][c4 + 1] = f2tf(bReg[ga][i].y);
                Bs[ga][r][c4 + 2] = f2tf(bReg[ga][i].z);
                Bs[ga][r][c4 + 3] = f2tf(bReg[ga][i].w);
            }
        __syncthreads();

        // prefetch next chunk while computing
        const int ktn = kt + KC;
        if (ktn < DW) {
            const int kg = ktn + ac4;
            const float* ap;
            if (kg < INW)             ap = x + (size_t)b_g * INW + kg;
            else if (kg < INW + CTXW) ap = c + (size_t)b_g * CTXW + (kg - INW);
            else                      ap = h + ((size_t)l * BAT + b_g) * STW + (kg - INW - CTXW);
            aReg = *(const float4*)ap;
            #pragma unroll
            for (int ga = 0; ga < 3; ga++)
                #pragma unroll
                for (int i = 0; i < 2; i++) {
                    const int idx = i * 256 + t;
                    const int r = idx >> 3, c4 = (idx & 7) << 2;
                    bReg[ga][i] = *(const float4*)(Wg[ga] + (size_t)(otile * 64 + r) * DW + ktn + c4);
                }
        }

        // compute 4 k-steps of 8
        #pragma unroll
        for (int ks = 0; ks < 4; ks++) {
            const int k0 = ks * 8;
            const unsigned a0 = As[wm * 16 + g][k0 + tg];
            const unsigned a1 = As[wm * 16 + g + 8][k0 + tg];
            const unsigned a2 = As[wm * 16 + g][k0 + tg + 4];
            const unsigned a3 = As[wm * 16 + g + 8][k0 + tg + 4];
            #pragma unroll
            for (int ga = 0; ga < 3; ga++)
                #pragma unroll
                for (int ni = 0; ni < 2; ni++) {
                    const int n0 = wn * 16 + ni * 8 + g;
                    const unsigned b0 = Bs[ga][n0][k0 + tg];
                    const unsigned b1 = Bs[ga][n0][k0 + tg + 4];
                    mma_tf32(acc[ga][ni], a0, a1, a2, a3, b0, b1);
                }
        }
        __syncthreads();
    }

    // epilogue: h_new = sigmoid(alpha)*tanh(phi) + sigmoid(beta)*h
    #pragma unroll
    for (int ni = 0; ni < 2; ni++)
        #pragma unroll
        for (int r = 0; r < 4; r++) {
            const int bm = mtile * 32 + wm * 16 + g + ((r & 2) ? 8 : 0);
            const int o  = otile * 64 + wn * 16 + ni * 8 + tg * 2 + (r & 1);
            const float phi = acc[0][ni][r] + phi_b[l * STW + o];
            const float al  = sigmoidf_(acc[1][ni][r] + alpha_b[l * STW + o]);
            const float be  = sigmoidf_(acc[2][ni][r] + beta_b[l * STW + o]);
            const size_t oi = ((size_t)l * BAT + bm) * STW + o;
            out[oi] = al * tanhf(phi) + be * h[oi];
        }
}

// ---------------------------------------------------------------------------
// u/v GEMM (merged N=512: u then v). wv = h_new|x|c.
// Block: M=32, N=64. 256 threads, warp tile 16x16 -> 1x2 mma.
// grid: (ntile=8, mtile=4, l=4) = 128 blocks.
// ---------------------------------------------------------------------------
__global__ __launch_bounds__(256)
void uv_mma(const float* __restrict__ hn, const float* __restrict__ x,
            const float* __restrict__ c,
            const float* __restrict__ u_w, const float* __restrict__ v_w,
            const float* __restrict__ u_b, const float* __restrict__ v_b)
{
    __shared__ unsigned As[32][KC + 1];
    __shared__ unsigned Bs[64][KC + 1];

    const int l = blockIdx.z;
    const int mtile = blockIdx.y;
    const int ntile = blockIdx.x;          // 0..7; which = ntile>>2
    const int t = threadIdx.x;
    const int lane = t & 31, w = t >> 5;
    const int wm = w >> 2, wn = w & 3;
    const int g = lane >> 2, tg = lane & 3;

    const int which = ntile >> 2;
    const int o_base = (ntile & 3) * 64;
    const float* W    = (which ? v_w : u_w) + (size_t)l * RW * DW;
    const float* bias = (which ? v_b : u_b) + l * RW;

    const int ar  = t >> 3;
    const int ac4 = (t & 7) << 2;
    const int b_g = mtile * 32 + ar;

    float4 aReg;
    float4 bReg[2];

    float acc[2][4];
    #pragma unroll
    for (int ni = 0; ni < 2; ni++)
        #pragma unroll
        for (int r = 0; r < 4; r++) acc[ni][r] = 0.0f;

    // prefetch chunk 0 (kt=0 -> h_new segment)
    aReg = *(const float4*)(hn + ((size_t)l * BAT + b_g) * STW + ac4);
    #pragma unroll
    for (int i = 0; i < 2; i++) {
        const int idx = i * 256 + t;
        const int r = idx >> 3, c4 = (idx & 7) << 2;
        bReg[i] = *(const float4*)(W + (size_t)(o_base + r) * DW + c4);
    }

    for (int kt = 0; kt < DW; kt += KC) {
        As[ar][ac4 + 0] = f2tf(aReg.x); As[ar][ac4 + 1] = f2tf(aReg.y);
        As[ar][ac4 + 2] = f2tf(aReg.z); As[ar][ac4 + 3] = f2tf(aReg.w);
        #pragma unroll
        for (int i = 0; i < 2; i++) {
            const int idx = i * 256 + t;
            const int r = idx >> 3, c4 = (idx & 7) << 2;
            Bs[r][c4 + 0] = f2tf(bReg[i].x);
            Bs[r][c4 + 1] = f2tf(bReg[i].y);
            Bs[r][c4 + 2] = f2tf(bReg[i].z);
            Bs[r][c4 + 3] = f2tf(bReg[i].w);
        }
        __syncthreads();

        const int ktn = kt + KC;
        if (ktn < DW) {
            const int kg = ktn + ac4;
            const float* ap;
            if (kg < STW)            ap = hn + ((size_t)l * BAT + b_g) * STW + kg;
            else if (kg < STW + INW) ap = x + (size_t)b_g * INW + (kg - STW);
            else                     ap = c + (size_t)b_g * CTXW + (kg - STW - INW);
            aReg = *(const float4*)ap;
            #pragma unroll
            for (int i = 0; i < 2; i++) {
                const int idx = i * 256 + t;
                const int r = idx >> 3, c4 = (idx & 7) << 2;
                bReg[i] = *(const float4*)(W + (size_t)(o_base + r) * DW + ktn + c4);
            }
        }

        #pragma unroll
        for (int ks = 0; ks < 4; ks++) {
            const int k0 = ks * 8;
            const unsigned a0 = As[wm * 16 + g][k0 + tg];
            const unsigned a1 = As[wm * 16 + g + 8][k0 + tg];
            const unsigned a2 = As[wm * 16 + g][k0 + tg + 4];
            const unsigned a3 = As[wm * 16 + g + 8][k0 + tg + 4];
            #pragma unroll
            for (int ni = 0; ni < 2; ni++) {
                const int n0 = wn * 16 + ni * 8 + g;
                const unsigned b0 = Bs[n0][k0 + tg];
                const unsigned b1 = Bs[n0][k0 + tg + 4];
                mma_tf32(acc[ni], a0, a1, a2, a3, b0, b1);
            }
        }
        __syncthreads();
    }

    #pragma unroll
    for (int ni = 0; ni < 2; ni++)
        #pragma unroll
        for (int r = 0; r < 4; r++) {
            const int bm = mtile * 32 + wm * 16 + g + ((r & 2) ? 8 : 0);
            const int o  = o_base + wn * 16 + ni * 8 + tg * 2 + (r & 1);
            g_uv[which][l][bm][o] = acc[ni][r] + bias[o];
        }
}

// ---------------------------------------------------------------------------
// M update, fused across all 4 levels so each M element is read exactly once:
// M_new[l] = (1-g)*M[l] + 0.5*g*(M[lu]+M[ld]) + e * u[l][i] * v[l][j]
// grid: (ichunk=8, b=128), 256 threads, float4 per thread.
// ---------------------------------------------------------------------------
__global__ __launch_bounds__(256)
void m_update(const float* __restrict__ M,
              const float* __restrict__ gamma_logits,
              const float* __restrict__ eta_logits,
              float* __restrict__ out)
{
    __shared__ float sv[4][256];
    __shared__ float su[4][32];
    __shared__ float sg[4], se[4];

    const int b  = blockIdx.y;
    const int ic = blockIdx.x;     // 0..7: 32-row chunk of i
    const int t  = threadIdx.x;

    for (int e = t; e < 1024; e += 256) {
        int l = e >> 8, j = e & 255;
        sv[l][j] = g_uv[1][l][b][j];
    }
    if (t < 128) {
        int l = t >> 5, i = t & 31;
        su[l][i] = g_uv[0][l][b][ic * 32 + i];
    }
    if (t < 4) { sg[t] = sigmoidf_(gamma_logits[t]); se[t] = sigmoidf_(eta_logits[t]); }
    __syncthreads();

    float* mout = out + H_SIZE;

    #pragma unroll 1
    for (int it = 0; it < 8; it++) {
        const int p  = it * 256 + t;
        const int i  = p >> 6;              // 0..31
        const int j4 = (p & 63) << 2;       // 0..252
        const int ig = ic * 32 + i;
        const size_t base = ((size_t)b * RW + ig) * CW + j4;   // within-level offset

        float4 m[4];
        #pragma unroll
        for (int l = 0; l < 4; l++)
            m[l] = *(const float4*)(M + (size_t)l * M_LVL_STRIDE + base);

        #pragma unroll
        for (int l = 0; l < 4; l++) {
            const int lu = (l == 0) ? 0 : l - 1;
            const int ld = (l == 3) ? 3 : l + 1;
            const float g = sg[l], e = se[l];
            const float uval = su[l][i];
            const float4 v = *(const float4*)&sv[l][j4];
            float4 o;
            o.x = (1.0f - g) * m[l].x + 0.5f * g * (m[lu].x + m[ld].x) + e * uval * v.x;
            o.y = (1.0f - g) * m[l].y + 0.5f * g * (m[lu].y + m[ld].y) + e * uval * v.y;
            o.z = (1.0f - g) * m[l].z + 0.5f * g * (m[lu].z + m[ld].z) + e * uval * v.z;
            o.w = (1.0f - g) * m[l].w + 0.5f * g * (m[lu].w + m[ld].w) + e * uval * v.w;
            *(float4*)(mout + (size_t)l * M_LVL_STRIDE + base) = o;
        }
    }
}

// ---------------------------------------------------------------------------
extern "C" void kernel_launch(void* const* d_in, const int* in_sizes, int n_in,
                              void* d_out, int out_size)
{
    const float* x       = (const float*)d_in[0];
    const float* c       = (const float*)d_in[1];
    const float* h       = (const float*)d_in[2];
    const float* M       = (const float*)d_in[3];
    const float* phi_w   = (const float*)d_in[4];
    const float* phi_b   = (const float*)d_in[5];
    const float* alpha_w = (const float*)d_in[6];
    const float* alpha_b = (const float*)d_in[7];
    const float* beta_w  = (const float*)d_in[8];
    const float* beta_b  = (const float*)d_in[9];
    const float* u_w     = (const float*)d_in[10];
    const float* u_b     = (const float*)d_in[11];
    const float* v_w     = (const float*)d_in[12];
    const float* v_b     = (const float*)d_in[13];
    const float* gamma_l = (const float*)d_in[14];
    const float* eta_l   = (const float*)d_in[15];

    float* out = (float*)d_out;

    // 1. fused 3-gate tf32 tensor-core GEMM + h_new epilogue -> out[0:H_SIZE]
    gate_hnew<<<dim3(8, 4, 4), 256>>>(x, c, h, phi_w, alpha_w, beta_w,
                                      phi_b, alpha_b, beta_b, out);
    // 2. u/v tf32 tensor-core GEMM (reads h_new from out) -> g_uv
    uv_mma<<<dim3(8, 4, 4), 256>>>(out, x, c, u_w, v_w, u_b, v_b);
    // 3. fused 4-level M update -> out[H_SIZE:]
    m_update<<<dim3(8, 128), 256>>>(M, gamma_l, eta_l, out);
}

// round 5
// speedup vs baseline: 2.5624x; 1.3471x over previous
#include <cuda_runtime.h>
#include <math.h>

#define LVL 4
#define BAT 128
#define INW 512
#define CTXW 512
#define STW 512
#define RW 256
#define CW 256
#define DW 1536
#define KC 32
#define NCHUNK (DW/KC)                /* 48 */
#define H_SIZE (LVL*BAT*STW)          /* 262144 */
#define M_LVL_STRIDE (BAT*RW*CW)      /* 8388608 */

// scratch (allocation-free rule: __device__ globals)
__device__ __align__(16) float g_gate[3][LVL][BAT][STW];  // phi/alpha/beta raw (3 MB)
__device__ __align__(16) float g_uv[2][LVL][BAT][RW];     // u,v raw (1 MB)

__device__ __forceinline__ float sigmoidf_(float x) { return 1.0f / (1.0f + __expf(-x)); }

__device__ __forceinline__ unsigned f2tf(float x) {
    unsigned r;
    asm("cvt.rna.tf32.f32 %0, %1;" : "=r"(r) : "f"(x));
    return r;
}

__device__ __forceinline__ void mma_tf32(float* d, unsigned a0, unsigned a1,
                                         unsigned a2, unsigned a3,
                                         unsigned b0, unsigned b1)
{
    asm volatile(
        "mma.sync.aligned.m16n8k8.row.col.f32.tf32.tf32.f32 "
        "{%0,%1,%2,%3}, {%4,%5,%6,%7}, {%8,%9}, {%0,%1,%2,%3};\n"
        : "+f"(d[0]), "+f"(d[1]), "+f"(d[2]), "+f"(d[3])
        : "r"(a0), "r"(a1), "r"(a2), "r"(a3), "r"(b0), "r"(b1));
}

__device__ __forceinline__ void cp16(void* dst, const void* src) {
    unsigned ds = (unsigned)__cvta_generic_to_shared(dst);
    asm volatile("cp.async.ca.shared.global [%0], [%1], 16;" :: "r"(ds), "l"(src));
}
__device__ __forceinline__ void cp_commit() { asm volatile("cp.async.commit_group;"); }
template<int N> __device__ __forceinline__ void cp_wait() {
    asm volatile("cp.async.wait_group %0;" :: "n"(N));
}

// ---------------------------------------------------------------------------
// Gate GEMM (un-fused): out_raw[gate][l][b][o] = gi[l,b,:] . W[l,o,:] + bias
// gi = x|c|h[l].  Block tile M=64(batch) x N=32(out), 64 threads (2 warps),
// warp tile 32x32 (m2 x n4 of m16n8k8).  cp.async double-buffered, stride-36
// smem rows (conflict-free fragment reads: bank = (4g+tg) mod 32).
// grid: (otile=16, mtile=2, z=l*3+gate=12) = 384 blocks.
// ---------------------------------------------------------------------------
__global__ __launch_bounds__(64)
void gate_gemm(const float* __restrict__ x, const float* __restrict__ c,
               const float* __restrict__ h,
               const float* __restrict__ phi_w, const float* __restrict__ alpha_w,
               const float* __restrict__ beta_w,
               const float* __restrict__ phi_b, const float* __restrict__ alpha_b,
               const float* __restrict__ beta_b)
{
    __shared__ float As[2][64][36];
    __shared__ float Bs[2][32][36];

    const int zz = blockIdx.z;
    const int l = zz / 3, gate = zz % 3;
    const int mtile = blockIdx.y;
    const int otile = blockIdx.x;
    const int t = threadIdx.x;
    const int w = t >> 5, lane = t & 31;
    const int g = lane >> 2, tg = lane & 3;

    const float* W    = (gate == 0 ? phi_w : gate == 1 ? alpha_w : beta_w) + (size_t)l * STW * DW;
    const float* bias = (gate == 0 ? phi_b : gate == 1 ? alpha_b : beta_b) + l * STW;

    float acc[2][4][4];
    #pragma unroll
    for (int mi = 0; mi < 2; mi++)
        #pragma unroll
        for (int ni = 0; ni < 4; ni++)
            #pragma unroll
            for (int r = 0; r < 4; r++) acc[mi][ni][r] = 0.0f;

    // ---- async loader: one KC=32 chunk into stage s ----
    auto load_chunk = [&](int kt, int s) {
        #pragma unroll
        for (int i = 0; i < 8; i++) {                 // A: 64 rows x 8 chunks
            const int idx = i * 64 + t;
            const int row = idx >> 3, ch = idx & 7;
            const int k = kt + ch * 4;
            const int b = mtile * 64 + row;
            const float* src;
            if (k < INW)              src = x + (size_t)b * INW + k;
            else if (k < INW + CTXW)  src = c + (size_t)b * CTXW + (k - INW);
            else                      src = h + ((size_t)l * BAT + b) * STW + (k - INW - CTXW);
            cp16(&As[s][row][ch * 4], src);
        }
        #pragma unroll
        for (int i = 0; i < 4; i++) {                 // B: 32 rows x 8 chunks
            const int idx = i * 64 + t;
            const int row = idx >> 3, ch = idx & 7;
            cp16(&Bs[s][row][ch * 4], W + (size_t)(otile * 32 + row) * DW + kt + ch * 4);
        }
        cp_commit();
    };

    load_chunk(0, 0);
    for (int it = 0; it < NCHUNK; ++it) {
        const int s = it & 1;
        if (it + 1 < NCHUNK) { load_chunk((it + 1) * KC, s ^ 1); cp_wait<1>(); }
        else                 { cp_wait<0>(); }
        __syncthreads();

        #pragma unroll
        for (int ks = 0; ks < 4; ks++) {
            const int k0 = ks * 8;
            unsigned a[2][4];
            #pragma unroll
            for (int mi = 0; mi < 2; mi++) {
                const int r0 = w * 32 + mi * 16;
                a[mi][0] = f2tf(As[s][r0 + g][k0 + tg]);
                a[mi][1] = f2tf(As[s][r0 + g + 8][k0 + tg]);
                a[mi][2] = f2tf(As[s][r0 + g][k0 + tg + 4]);
                a[mi][3] = f2tf(As[s][r0 + g + 8][k0 + tg + 4]);
            }
            unsigned bb[4][2];
            #pragma unroll
            for (int ni = 0; ni < 4; ni++) {
                const int n0 = ni * 8 + g;
                bb[ni][0] = f2tf(Bs[s][n0][k0 + tg]);
                bb[ni][1] = f2tf(Bs[s][n0][k0 + tg + 4]);
            }
            #pragma unroll
            for (int mi = 0; mi < 2; mi++)
                #pragma unroll
                for (int ni = 0; ni < 4; ni++)
                    mma_tf32(acc[mi][ni], a[mi][0], a[mi][1], a[mi][2], a[mi][3],
                             bb[ni][0], bb[ni][1]);
        }
        __syncthreads();
    }

    // epilogue: raw (+bias) to scratch
    #pragma unroll
    for (int mi = 0; mi < 2; mi++) {
        const int r0 = mtile * 64 + w * 32 + mi * 16;
        #pragma unroll
        for (int ni = 0; ni < 4; ni++) {
            const int o0 = otile * 32 + ni * 8 + tg * 2;
            const float b0 = bias[o0], b1 = bias[o0 + 1];
            float2 v0 = { acc[mi][ni][0] + b0, acc[mi][ni][1] + b1 };
            float2 v1 = { acc[mi][ni][2] + b0, acc[mi][ni][3] + b1 };
            *(float2*)&g_gate[gate][l][r0 + g][o0]     = v0;
            *(float2*)&g_gate[gate][l][r0 + g + 8][o0] = v1;
        }
    }
}

// ---------------------------------------------------------------------------
// h_new = sigmoid(alpha) * tanh(phi) + sigmoid(beta) * h    -> d_out[0:H_SIZE]
// ---------------------------------------------------------------------------
__global__ __launch_bounds__(256)
void hnew_kernel(const float* __restrict__ h, float* __restrict__ out)
{
    const int idx = blockIdx.x * blockDim.x + threadIdx.x;
    if (idx >= H_SIZE) return;
    const float* g = &g_gate[0][0][0][0];
    float phi   = g[idx];
    float alpha = g[H_SIZE + idx];
    float beta  = g[2 * H_SIZE + idx];
    out[idx] = sigmoidf_(alpha) * tanhf(phi) + sigmoidf_(beta) * h[idx];
}

// ---------------------------------------------------------------------------
// u/v GEMM: same structure.  wv = h_new|x|c.  Block M=64 x N=32.
// grid: (otile=8, mtile=2, z=l*2+which=8) = 128 blocks.
// ---------------------------------------------------------------------------
__global__ __launch_bounds__(64)
void uv_gemm(const float* __restrict__ hn, const float* __restrict__ x,
             const float* __restrict__ c,
             const float* __restrict__ u_w, const float* __restrict__ v_w,
             const float* __restrict__ u_b, const float* __restrict__ v_b)
{
    __shared__ float As[2][64][36];
    __shared__ float Bs[2][32][36];

    const int zz = blockIdx.z;
    const int l = zz >> 1, which = zz & 1;
    const int mtile = blockIdx.y;
    const int otile = blockIdx.x;
    const int t = threadIdx.x;
    const int w = t >> 5, lane = t & 31;
    const int g = lane >> 2, tg = lane & 3;

    const float* W    = (which ? v_w : u_w) + (size_t)l * RW * DW;
    const float* bias = (which ? v_b : u_b) + l * RW;

    float acc[2][4][4];
    #pragma unroll
    for (int mi = 0; mi < 2; mi++)
        #pragma unroll
        for (int ni = 0; ni < 4; ni++)
            #pragma unroll
            for (int r = 0; r < 4; r++) acc[mi][ni][r] = 0.0f;

    auto load_chunk = [&](int kt, int s) {
        #pragma unroll
        for (int i = 0; i < 8; i++) {
            const int idx = i * 64 + t;
            const int row = idx >> 3, ch = idx & 7;
            const int k = kt + ch * 4;
            const int b = mtile * 64 + row;
            const float* src;
            if (k < STW)              src = hn + ((size_t)l * BAT + b) * STW + k;
            else if (k < STW + INW)   src = x + (size_t)b * INW + (k - STW);
            else                      src = c + (size_t)b * CTXW + (k - STW - INW);
            cp16(&As[s][row][ch * 4], src);
        }
        #pragma unroll
        for (int i = 0; i < 4; i++) {
            const int idx = i * 64 + t;
            const int row = idx >> 3, ch = idx & 7;
            cp16(&Bs[s][row][ch * 4], W + (size_t)(otile * 32 + row) * DW + kt + ch * 4);
        }
        cp_commit();
    };

    load_chunk(0, 0);
    for (int it = 0; it < NCHUNK; ++it) {
        const int s = it & 1;
        if (it + 1 < NCHUNK) { load_chunk((it + 1) * KC, s ^ 1); cp_wait<1>(); }
        else                 { cp_wait<0>(); }
        __syncthreads();

        #pragma unroll
        for (int ks = 0; ks < 4; ks++) {
            const int k0 = ks * 8;
            unsigned a[2][4];
            #pragma unroll
            for (int mi = 0; mi < 2; mi++) {
                const int r0 = w * 32 + mi * 16;
                a[mi][0] = f2tf(As[s][r0 + g][k0 + tg]);
                a[mi][1] = f2tf(As[s][r0 + g + 8][k0 + tg]);
                a[mi][2] = f2tf(As[s][r0 + g][k0 + tg + 4]);
                a[mi][3] = f2tf(As[s][r0 + g + 8][k0 + tg + 4]);
            }
            unsigned bb[4][2];
            #pragma unroll
            for (int ni = 0; ni < 4; ni++) {
                const int n0 = ni * 8 + g;
                bb[ni][0] = f2tf(Bs[s][n0][k0 + tg]);
                bb[ni][1] = f2tf(Bs[s][n0][k0 + tg + 4]);
            }
            #pragma unroll
            for (int mi = 0; mi < 2; mi++)
                #pragma unroll
                for (int ni = 0; ni < 4; ni++)
                    mma_tf32(acc[mi][ni], a[mi][0], a[mi][1], a[mi][2], a[mi][3],
                             bb[ni][0], bb[ni][1]);
        }
        __syncthreads();
    }

    #pragma unroll
    for (int mi = 0; mi < 2; mi++) {
        const int r0 = mtile * 64 + w * 32 + mi * 16;
        #pragma unroll
        for (int ni = 0; ni < 4; ni++) {
            const int o0 = otile * 32 + ni * 8 + tg * 2;
            const float b0 = bias[o0], b1 = bias[o0 + 1];
            float2 v0 = { acc[mi][ni][0] + b0, acc[mi][ni][1] + b1 };
            float2 v1 = { acc[mi][ni][2] + b0, acc[mi][ni][3] + b1 };
            *(float2*)&g_uv[which][l][r0 + g][o0]     = v0;
            *(float2*)&g_uv[which][l][r0 + g + 8][o0] = v1;
        }
    }
}

// ---------------------------------------------------------------------------
// M update, fused across all 4 levels so each M element is read exactly once:
// M_new[l] = (1-g)*M[l] + 0.5*g*(M[lu]+M[ld]) + e * u[l][i] * v[l][j]
// grid: (ichunk=8, b=128), 256 threads, float4 per thread.
// ---------------------------------------------------------------------------
__global__ __launch_bounds__(256)
void m_update(const float* __restrict__ M,
              const float* __restrict__ gamma_logits,
              const float* __restrict__ eta_logits,
              float* __restrict__ out)
{
    __shared__ float sv[4][256];
    __shared__ float su[4][32];
    __shared__ float sg[4], se[4];

    const int b  = blockIdx.y;
    const int ic = blockIdx.x;
    const int t  = threadIdx.x;

    for (int e = t; e < 1024; e += 256) {
        int l = e >> 8, j = e & 255;
        sv[l][j] = g_uv[1][l][b][j];
    }
    if (t < 128) {
        int l = t >> 5, i = t & 31;
        su[l][i] = g_uv[0][l][b][ic * 32 + i];
    }
    if (t < 4) { sg[t] = sigmoidf_(gamma_logits[t]); se[t] = sigmoidf_(eta_logits[t]); }
    __syncthreads();

    float* mout = out + H_SIZE;

    #pragma unroll 1
    for (int it = 0; it < 8; it++) {
        const int p  = it * 256 + t;
        const int i  = p >> 6;
        const int j4 = (p & 63) << 2;
        const int ig = ic * 32 + i;
        const size_t base = ((size_t)b * RW + ig) * CW + j4;

        float4 m[4];
        #pragma unroll
        for (int l = 0; l < 4; l++)
            m[l] = *(const float4*)(M + (size_t)l * M_LVL_STRIDE + base);

        #pragma unroll
        for (int l = 0; l < 4; l++) {
            const int lu = (l == 0) ? 0 : l - 1;
            const int ld = (l == 3) ? 3 : l + 1;
            const float g = sg[l], e = se[l];
            const float uval = su[l][i];
            const float4 v = *(const float4*)&sv[l][j4];
            float4 o;
            o.x = (1.0f - g) * m[l].x + 0.5f * g * (m[lu].x + m[ld].x) + e * uval * v.x;
            o.y = (1.0f - g) * m[l].y + 0.5f * g * (m[lu].y + m[ld].y) + e * uval * v.y;
            o.z = (1.0f - g) * m[l].z + 0.5f * g * (m[lu].z + m[ld].z) + e * uval * v.z;
            o.w = (1.0f - g) * m[l].w + 0.5f * g * (m[lu].w + m[ld].w) + e * uval * v.w;
            *(float4*)(mout + (size_t)l * M_LVL_STRIDE + base) = o;
        }
    }
}

// ---------------------------------------------------------------------------
extern "C" void kernel_launch(void* const* d_in, const int* in_sizes, int n_in,
                              void* d_out, int out_size)
{
    const float* x       = (const float*)d_in[0];
    const float* c       = (const float*)d_in[1];
    const float* h       = (const float*)d_in[2];
    const float* M       = (const float*)d_in[3];
    const float* phi_w   = (const float*)d_in[4];
    const float* phi_b   = (const float*)d_in[5];
    const float* alpha_w = (const float*)d_in[6];
    const float* alpha_b = (const float*)d_in[7];
    const float* beta_w  = (const float*)d_in[8];
    const float* beta_b  = (const float*)d_in[9];
    const float* u_w     = (const float*)d_in[10];
    const float* u_b     = (const float*)d_in[11];
    const float* v_w     = (const float*)d_in[12];
    const float* v_b     = (const float*)d_in[13];
    const float* gamma_l = (const float*)d_in[14];
    const float* eta_l   = (const float*)d_in[15];

    float* out = (float*)d_out;

    // 1. gate GEMMs (tf32 tensor cores, cp.async pipeline) -> g_gate
    gate_gemm<<<dim3(16, 2, 12), 64>>>(x, c, h, phi_w, alpha_w, beta_w,
                                       phi_b, alpha_b, beta_b);
    // 2. h_new -> out[0:H_SIZE]
    hnew_kernel<<<H_SIZE / 256, 256>>>(h, out);
    // 3. u/v GEMMs (read h_new from out) -> g_uv
    uv_gemm<<<dim3(8, 2, 8), 64>>>(out, x, c, u_w, v_w, u_b, v_b);
    // 4. fused 4-level M update -> out[H_SIZE:]
    m_update<<<dim3(8, 128), 256>>>(M, gamma_l, eta_l, out);
}